// round 13
// baseline (speedup 1.0000x reference)
#include <cuda_runtime.h>
#include <cuda_bf16.h>
#include <cstdint>

// ---------------------------------------------------------------------------
// Problem constants
// ---------------------------------------------------------------------------
#define NPF 20000
#define NGW 100000
#define NSW 30000
#define D   128

#define EPG 1600000
#define EGP 640000
#define EPS 480000
#define ESP 320000
#define ETOT (EPG + EGP + EPS + ESP)

#define NTOT (NGW + NPF + NSW + NPF)

// ---------------------------------------------------------------------------
// Device scratch
// ---------------------------------------------------------------------------
__device__ float g_mean_gw[(size_t)NGW * D];
__device__ float g_mean_sw[(size_t)NSW * D];
__device__ float g_mean_gp[(size_t)NPF * D];
__device__ float g_mean_sp[(size_t)NPF * D];
__device__ int   g_cnt[NTOT];
__device__ int   g_rowptr[NTOT];
__device__ int   g_cursor[NTOT];
__device__ int   g_perm[ETOT];
__device__ int   g_partials[4 * 128];
__device__ float g_wr_comb[D * D];

// ---------------------------------------------------------------------------
// small utility kernels
// ---------------------------------------------------------------------------
__global__ void zero_int_kernel(int* __restrict__ p, int n4) {
    int i = blockIdx.x * blockDim.x + threadIdx.x;
    if (i < n4) reinterpret_cast<int4*>(p)[i] = make_int4(0, 0, 0, 0);
}

__global__ void addw_kernel(const float* __restrict__ a, const float* __restrict__ b,
                            float* __restrict__ o) {
    int i = blockIdx.x * blockDim.x + threadIdx.x;
    if (i < D * D) o[i] = a[i] + b[i];
}

// ---------------------------------------------------------------------------
// Fused CSR build (proven)
// ---------------------------------------------------------------------------
__global__ void hist_f(const int* __restrict__ pgd, const int* __restrict__ gpd,
                       const int* __restrict__ psd, const int* __restrict__ spd,
                       int* __restrict__ cnt) {
    int e = blockIdx.x * blockDim.x + threadIdx.x;
    if (e < EPG)                        atomicAdd(&cnt[pgd[e]], 1);
    else if (e < EPG + EGP)             atomicAdd(&cnt[NGW + gpd[e - EPG]], 1);
    else if (e < EPG + EGP + EPS)       atomicAdd(&cnt[NGW + NPF + psd[e - EPG - EGP]], 1);
    else if (e < ETOT)                  atomicAdd(&cnt[NGW + NPF + NSW + spd[e - EPG - EGP - EPS]], 1);
}

__global__ void scan_reduce_f(const int* __restrict__ cnt, int* __restrict__ partials) {
    const int nbs[4]  = {98, 20, 30, 20};
    const int offs[4] = {0, NGW, NGW + NPF, NGW + NPF + NSW};
    const int ns[4]   = {NGW, NPF, NSW, NPF};
    int r = blockIdx.y;
    if ((int)blockIdx.x >= nbs[r]) return;
    const int* c = cnt + offs[r];
    int n = ns[r];
    __shared__ int s[256];
    int t = threadIdx.x;
    int base = blockIdx.x * 1024 + t * 4;
    int sum = 0;
#pragma unroll
    for (int j = 0; j < 4; j++) {
        int idx = base + j;
        if (idx < n) sum += c[idx];
    }
    s[t] = sum;
    __syncthreads();
    for (int off = 128; off > 0; off >>= 1) {
        if (t < off) s[t] += s[t + off];
        __syncthreads();
    }
    if (t == 0) partials[r * 128 + blockIdx.x] = s[0];
}

__global__ void scan_partials_all(int* __restrict__ partials) {
    __shared__ int s[128];
    int t = threadIdx.x;
    for (int r = 0; r < 4; r++) {
        int v = partials[r * 128 + t];
        s[t] = v;
        __syncthreads();
        for (int off = 1; off < 128; off <<= 1) {
            int y = (t >= off) ? s[t - off] : 0;
            __syncthreads();
            s[t] += y;
            __syncthreads();
        }
        partials[r * 128 + t] = s[t] - v;
        __syncthreads();
    }
}

__global__ void scan_write_f(const int* __restrict__ cnt,
                             const int* __restrict__ partials,
                             int* __restrict__ rowptr,
                             int* __restrict__ cursor) {
    const int nbs[4]  = {98, 20, 30, 20};
    const int offs[4] = {0, NGW, NGW + NPF, NGW + NPF + NSW};
    const int ns[4]   = {NGW, NPF, NSW, NPF};
    int r = blockIdx.y;
    if ((int)blockIdx.x >= nbs[r]) return;
    const int* c = cnt + offs[r];
    int* rp = rowptr + offs[r];
    int* cu = cursor + offs[r];
    int n = ns[r];

    __shared__ int wsum[8];
    __shared__ int woff[8];
    int t = threadIdx.x;
    int lane = t & 31, warp = t >> 5;
    int base = blockIdx.x * 1024 + t * 4;
    int v[4];
    int tsum = 0;
#pragma unroll
    for (int j = 0; j < 4; j++) {
        int idx = base + j;
        v[j] = (idx < n) ? c[idx] : 0;
        tsum += v[j];
    }
    int incl = tsum;
#pragma unroll
    for (int o = 1; o < 32; o <<= 1) {
        int y = __shfl_up_sync(0xffffffffu, incl, o);
        if (lane >= o) incl += y;
    }
    int excl = incl - tsum;
    if (lane == 31) wsum[warp] = incl;
    __syncthreads();
    if (t == 0) {
        int rr = 0;
        for (int i = 0; i < 8; i++) { woff[i] = rr; rr += wsum[i]; }
    }
    __syncthreads();
    int run = partials[r * 128 + blockIdx.x] + woff[warp] + excl;
#pragma unroll
    for (int j = 0; j < 4; j++) {
        int idx = base + j;
        if (idx < n) { rp[idx] = run; cu[idx] = run; run += v[j]; }
    }
}

__global__ void permute_f(const int* __restrict__ pgs, const int* __restrict__ pgd,
                          const int* __restrict__ gps, const int* __restrict__ gpd,
                          const int* __restrict__ pss, const int* __restrict__ psd,
                          const int* __restrict__ sps, const int* __restrict__ spd,
                          int* __restrict__ cursor, int* __restrict__ perm) {
    int e = blockIdx.x * blockDim.x + threadIdx.x;
    const int *src, *dst;
    int off, poff, le;
    if (e < EPG)                  { src = pgs; dst = pgd; off = 0;               poff = 0;               le = e; }
    else if (e < EPG + EGP)       { src = gps; dst = gpd; off = NGW;             poff = EPG;             le = e - EPG; }
    else if (e < EPG + EGP + EPS) { src = pss; dst = psd; off = NGW + NPF;       poff = EPG + EGP;       le = e - EPG - EGP; }
    else if (e < ETOT)            { src = sps; dst = spd; off = NGW + NPF + NSW; poff = EPG + EGP + EPS; le = e - EPG - EGP - EPS; }
    else return;
    int pos = atomicAdd(&cursor[off + dst[le]], 1);
    perm[poff + pos] = src[le];
}

// ---------------------------------------------------------------------------
// Job descriptors
// ---------------------------------------------------------------------------
struct GemmJob {
    const float *A0, *A1, *A2;
    const float *W0, *W1, *W2;
    const float *bias1, *bias2, *whead, *bhead;
    float* out;
    int row_base, n_rows, nseg, mode, nblocks;
};
struct AggJob {
    const float* x;
    const int* rowptr;
    const int* perm;
    float* outmean;
    int n0, n1, N, E, nblocks;
};

// ---------------------------------------------------------------------------
// agg path: warp per node, 8-edge MLP batching (proven in R12, correct)
// ---------------------------------------------------------------------------
__device__ __forceinline__ void agg_path(const AggJob& jb, int rblk, int t) {
    int w = jb.n0 + rblk * 8 + (t >> 5);
    int lane = t & 31;
    if (w >= jb.n1) return;

    int start = jb.rowptr[w];
    int end   = (w + 1 < jb.N) ? jb.rowptr[w + 1] : jb.E;
    const float* x = jb.x;

    float4 acc = make_float4(0.f, 0.f, 0.f, 0.f);
    for (int e0 = start; e0 < end; e0 += 32) {
        int idx = (e0 + lane < end) ? jb.perm[e0 + lane] : 0;
        int m = min(32, end - e0);
        int j = 0;
        for (; j + 8 <= m; j += 8) {
            float4 v[8];
#pragma unroll
            for (int q = 0; q < 8; q++) {
                int s = __shfl_sync(0xffffffffu, idx, j + q);
                v[q] = *reinterpret_cast<const float4*>(x + (size_t)s * D + lane * 4);
            }
#pragma unroll
            for (int q = 0; q < 8; q++) {
                acc.x += v[q].x; acc.y += v[q].y; acc.z += v[q].z; acc.w += v[q].w;
            }
        }
        for (; j < m; j++) {
            int s = __shfl_sync(0xffffffffu, idx, j);
            float4 v = *reinterpret_cast<const float4*>(x + (size_t)s * D + lane * 4);
            acc.x += v.x; acc.y += v.y; acc.z += v.z; acc.w += v.w;
        }
    }
    float inv = 1.0f / fmaxf((float)(end - start), 1.0f);
    acc.x *= inv; acc.y *= inv; acc.z *= inv; acc.w *= inv;
    *reinterpret_cast<float4*>(jb.outmean + (size_t)w * D + lane * 4) = acc;
}

// ---------------------------------------------------------------------------
// gemm path: proven f32x2 128x128-tile GEMM, runtime nseg/mode (R12, correct)
// ---------------------------------------------------------------------------
__device__ __forceinline__ void gemm_path(const GemmJob& g, int bid, int t,
                                          float (*As)[132], float (*Ws)[132],
                                          float* red)
{
    const int row0 = g.row_base + bid * 128;
    const int trow = t >> 4;
    const int tcol = t & 15;

    const float* Aseg[3] = {g.A0, g.A1, g.A2};
    const float* Wseg[3] = {g.W0, g.W1, g.W2};

    unsigned long long accp[8][4];
#pragma unroll
    for (int i = 0; i < 8; i++)
#pragma unroll
        for (int j2 = 0; j2 < 4; j2++) accp[i][j2] = 0ull;

    const int nchunks = g.nseg * 8;
    for (int ch = 0; ch < nchunks; ch++) {
        const int seg  = ch >> 3;
        const int kin0 = (ch & 7) * 16;
        const float* A = Aseg[seg];
        const float* W = Wseg[seg];

#pragma unroll
        for (int it = 0; it < 2; it++) {
            int idx  = t + it * 256;
            int row  = idx >> 2;
            int q    = idx & 3;
            int grow = row0 + row;
            float4 v = make_float4(0.f, 0.f, 0.f, 0.f);
            if (grow < g.n_rows)
                v = *reinterpret_cast<const float4*>(A + (size_t)grow * D + kin0 + q * 4);
            As[q * 4 + 0][row] = v.x;
            As[q * 4 + 1][row] = v.y;
            As[q * 4 + 2][row] = v.z;
            As[q * 4 + 3][row] = v.w;
        }
#pragma unroll
        for (int it = 0; it < 2; it++) {
            int idx = t + it * 256;
            int kk  = idx >> 5;
            int cq  = idx & 31;
            float4 w = *reinterpret_cast<const float4*>(W + (size_t)(kin0 + kk) * D + cq * 4);
            *reinterpret_cast<float4*>(&Ws[kk][cq * 4]) = w;
        }
        __syncthreads();

#pragma unroll
        for (int kk = 0; kk < 16; kk++) {
            float4 a0 = *reinterpret_cast<const float4*>(&As[kk][trow * 4]);
            float4 a1 = *reinterpret_cast<const float4*>(&As[kk][64 + trow * 4]);
            unsigned long long wp[4];
            wp[0] = *reinterpret_cast<const unsigned long long*>(&Ws[kk][tcol * 4]);
            wp[1] = *reinterpret_cast<const unsigned long long*>(&Ws[kk][tcol * 4 + 2]);
            wp[2] = *reinterpret_cast<const unsigned long long*>(&Ws[kk][64 + tcol * 4]);
            wp[3] = *reinterpret_cast<const unsigned long long*>(&Ws[kk][64 + tcol * 4 + 2]);
            float a[8] = {a0.x, a0.y, a0.z, a0.w, a1.x, a1.y, a1.z, a1.w};
#pragma unroll
            for (int i = 0; i < 8; i++) {
                unsigned long long ap;
                asm("mov.b64 %0, {%1, %1};" : "=l"(ap) : "f"(a[i]));
#pragma unroll
                for (int j2 = 0; j2 < 4; j2++)
                    asm("fma.rn.f32x2 %0, %1, %2, %0;"
                        : "+l"(accp[i][j2]) : "l"(ap), "l"(wp[j2]));
            }
        }
        __syncthreads();
    }

    float acc[8][8];
#pragma unroll
    for (int i = 0; i < 8; i++)
#pragma unroll
        for (int j2 = 0; j2 < 4; j2++)
            asm("mov.b64 {%0, %1}, %2;"
                : "=f"(acc[i][2 * j2]), "=f"(acc[i][2 * j2 + 1]) : "l"(accp[i][j2]));

    int cidx[8], ridx[8];
#pragma unroll
    for (int j = 0; j < 8; j++)
        cidx[j] = (j < 4) ? (tcol * 4 + j) : (64 + tcol * 4 + (j - 4));
#pragma unroll
    for (int i = 0; i < 8; i++)
        ridx[i] = (i < 4) ? (trow * 4 + i) : (64 + trow * 4 + (i - 4));

    float b[8];
#pragma unroll
    for (int j = 0; j < 8; j++)
        b[j] = g.bias1[cidx[j]] + (g.bias2 ? g.bias2[cidx[j]] : 0.f);

    if (g.mode == 0) {
#pragma unroll
        for (int i = 0; i < 8; i++) {
            int grow = row0 + ridx[i];
            if (grow < g.n_rows) {
#pragma unroll
                for (int j = 0; j < 8; j++)
                    g.out[(size_t)grow * D + cidx[j]] = fmaxf(acc[i][j] + b[j], 0.f);
            }
        }
    } else {
        float wh[8];
#pragma unroll
        for (int j = 0; j < 8; j++) wh[j] = g.whead[cidx[j]];
        if (t < 128) red[t] = 0.f;
        __syncthreads();
#pragma unroll
        for (int i = 0; i < 8; i++) {
            float partial = 0.f;
#pragma unroll
            for (int j = 0; j < 8; j++)
                partial += fmaxf(acc[i][j] + b[j], 0.f) * wh[j];
            atomicAdd(&red[ridx[i]], partial);
        }
        __syncthreads();
        if (t < 128) {
            int grow = row0 + t;
            if (grow < g.n_rows) g.out[grow] = red[t] + g.bhead[0];
        }
    }
}

// ---------------------------------------------------------------------------
// mega kernel: ≤2 gemm jobs (FIRST in bid order; ≤ ~1 wave so one lands per
// SM while agg blocks churn in the second resident slot) + ≤3 agg jobs.
// ---------------------------------------------------------------------------
__global__ __launch_bounds__(256, 2) void mega_kernel(
    GemmJob g0, GemmJob g1, AggJob a0, AggJob a1, AggJob a2)
{
    __shared__ float As[16][132];
    __shared__ float Ws[16][132];
    __shared__ float red[128];

    int bid = blockIdx.x;
    int t = threadIdx.x;

    if (bid < g0.nblocks) { gemm_path(g0, bid, t, As, Ws, red); return; }
    bid -= g0.nblocks;
    if (bid < g1.nblocks) { gemm_path(g1, bid, t, As, Ws, red); return; }
    bid -= g1.nblocks;
    if (bid < a0.nblocks) { agg_path(a0, bid, t); return; }
    bid -= a0.nblocks;
    if (bid < a1.nblocks) { agg_path(a1, bid, t); return; }
    bid -= a1.nblocks;
    if (bid < a2.nblocks) { agg_path(a2, bid, t); }
}

// ---------------------------------------------------------------------------
// Launch
// ---------------------------------------------------------------------------
extern "C" void kernel_launch(void* const* d_in, const int* in_sizes, int n_in,
                              void* d_out, int out_size)
{
    const float* x_pfas = (const float*)d_in[0];
    const float* x_gw   = (const float*)d_in[1];
    const float* x_sw   = (const float*)d_in[2];
    const int* ei_pg_src = (const int*)d_in[3];
    const int* ei_pg_dst = (const int*)d_in[4];
    const int* ei_gp_src = (const int*)d_in[5];
    const int* ei_gp_dst = (const int*)d_in[6];
    const int* ei_ps_src = (const int*)d_in[7];
    const int* ei_ps_dst = (const int*)d_in[8];
    const int* ei_sp_src = (const int*)d_in[9];
    const int* ei_sp_dst = (const int*)d_in[10];
    const float* Wl_pg = (const float*)d_in[11];
    const float* bl_pg = (const float*)d_in[12];
    const float* Wr_pg = (const float*)d_in[13];
    const float* Wl_gp = (const float*)d_in[14];
    const float* bl_gp = (const float*)d_in[15];
    const float* Wr_gp = (const float*)d_in[16];
    const float* Wl_ps = (const float*)d_in[17];
    const float* bl_ps = (const float*)d_in[18];
    const float* Wr_ps = (const float*)d_in[19];
    const float* Wl_sp = (const float*)d_in[20];
    const float* bl_sp = (const float*)d_in[21];
    const float* Wr_sp = (const float*)d_in[22];
    const float* W_gw  = (const float*)d_in[23];
    const float* b_gw  = (const float*)d_in[24];
    const float* W_sw  = (const float*)d_in[25];
    const float* b_sw  = (const float*)d_in[26];

    float* out = (float*)d_out;
    float* out_hpf = out;                       // [20000, 128]
    float* out_gw  = out + (size_t)NPF * D;     // [100000]
    float* out_sw  = out_gw + NGW;              // [30000]

    static float *mean_gw = nullptr, *mean_sw = nullptr, *mean_gp = nullptr, *mean_sp = nullptr;
    static float *wr_comb = nullptr;
    static int *cnt = nullptr, *rowptr = nullptr, *cursor = nullptr, *perm = nullptr, *partials = nullptr;
    if (!mean_gw) {
        cudaGetSymbolAddress((void**)&mean_gw, g_mean_gw);
        cudaGetSymbolAddress((void**)&mean_sw, g_mean_sw);
        cudaGetSymbolAddress((void**)&mean_gp, g_mean_gp);
        cudaGetSymbolAddress((void**)&mean_sp, g_mean_sp);
        cudaGetSymbolAddress((void**)&wr_comb, g_wr_comb);
        cudaGetSymbolAddress((void**)&cnt, g_cnt);
        cudaGetSymbolAddress((void**)&rowptr, g_rowptr);
        cudaGetSymbolAddress((void**)&cursor, g_cursor);
        cudaGetSymbolAddress((void**)&perm, g_perm);
        cudaGetSymbolAddress((void**)&partials, g_partials);
    }

    const int off_pg = 0;
    const int off_gp = NGW;
    const int off_ps = NGW + NPF;
    const int off_sp = NGW + NPF + NSW;
    const int poff_pg = 0;
    const int poff_gp = EPG;
    const int poff_ps = EPG + EGP;
    const int poff_sp = EPG + EGP + EPS;

    // ---- 1) zero counters + fold Wr weights ----
    zero_int_kernel<<<(NTOT / 4 + 255) / 256, 256>>>(cnt, NTOT / 4);
    addw_kernel<<<(D * D + 255) / 256, 256>>>(Wr_gp, Wr_sp, wr_comb);

    // ---- 2) fused CSR build ----
    hist_f<<<(ETOT + 255) / 256, 256>>>(ei_pg_dst, ei_gp_dst, ei_ps_dst, ei_sp_dst, cnt);
    {
        dim3 g(98, 4);
        scan_reduce_f<<<g, 256>>>(cnt, partials);
        scan_partials_all<<<1, 128>>>(partials);
        scan_write_f<<<g, 256>>>(cnt, partials, rowptr, cursor);
    }
    permute_f<<<(ETOT + 255) / 256, 256>>>(
        ei_pg_src, ei_pg_dst, ei_gp_src, ei_gp_dst,
        ei_ps_src, ei_ps_dst, ei_sp_src, ei_sp_dst,
        cursor, perm);

    // ---- 3) phased heterogeneous execution ----
    GemmJob GZ = {};
    AggJob  AZ = {};

    auto mkAgg = [&](const float* x, int off, int poff, int N, int E,
                     float* mean, int n0, int n1) {
        AggJob j;
        j.x = x; j.rowptr = rowptr + off; j.perm = perm + poff;
        j.outmean = mean; j.n0 = n0; j.n1 = n1; j.N = N; j.E = E;
        j.nblocks = (n1 - n0 + 7) / 8;
        return j;
    };
    auto mkGemm = [&](const float* A0, const float* A1, const float* A2,
                      const float* W0, const float* W1, const float* W2,
                      const float* b1, const float* b2,
                      const float* wh, const float* bh,
                      float* o, int row_base, int row_end, int N, int nseg, int mode) {
        GemmJob j;
        j.A0 = A0; j.A1 = A1; j.A2 = A2; j.W0 = W0; j.W1 = W1; j.W2 = W2;
        j.bias1 = b1; j.bias2 = b2; j.whead = wh; j.bhead = bh;
        j.out = o; j.row_base = row_base; j.n_rows = N;
        j.nseg = nseg; j.mode = mode;
        j.nblocks = (row_end - row_base + 127) / 128;
        return j;
    };
    auto launch = [&](GemmJob g0, GemmJob g1, AggJob a0, AggJob a1, AggJob a2) {
        int nb = g0.nblocks + g1.nblocks + a0.nblocks + a1.nblocks + a2.nblocks;
        if (nb > 0) mega_kernel<<<nb, 256>>>(g0, g1, a0, a1, a2);
    };

    // --- row splits ---
    const int pf_h  = 10240;            // pfas half (80 gemm blocks)
    const int sw_h  = 10240;            // sw first chunk
    // gw agg slices: 5 x 20000 rows
    const int ga[6] = {0, 20000, 40000, 60000, 80000, NGW};
    // gw gemm slices: 5 x ~156 blocks (multiples of 128 rows; each <= agg'd rows)
    const int gg[6] = {0, 19968, 39936, 59904, 79872, NGW};

    // agg jobs
    AggJob aGP1 = mkAgg(x_gw, off_gp, poff_gp, NPF, EGP, mean_gp, 0, pf_h);
    AggJob aSP1 = mkAgg(x_sw, off_sp, poff_sp, NPF, ESP, mean_sp, 0, pf_h);
    AggJob aGP2 = mkAgg(x_gw, off_gp, poff_gp, NPF, EGP, mean_gp, pf_h, NPF);
    AggJob aSP2 = mkAgg(x_sw, off_sp, poff_sp, NPF, ESP, mean_sp, pf_h, NPF);
    AggJob aSW1 = mkAgg(x_pfas, off_ps, poff_ps, NSW, EPS, mean_sw, 0, sw_h);
    AggJob aSW2 = mkAgg(x_pfas, off_ps, poff_ps, NSW, EPS, mean_sw, sw_h, NSW);
    AggJob aGW[5];
    for (int i = 0; i < 5; i++)
        aGW[i] = mkAgg(x_pfas, off_pg, poff_pg, NGW, EPG, mean_gw, ga[i], ga[i + 1]);

    // gemm jobs
    GemmJob gPF1 = mkGemm(mean_gp, mean_sp, x_pfas, Wl_gp, Wl_sp, wr_comb,
                          bl_gp, bl_sp, nullptr, nullptr,
                          out_hpf, 0, pf_h, NPF, 3, 0);
    GemmJob gPF2 = mkGemm(mean_gp, mean_sp, x_pfas, Wl_gp, Wl_sp, wr_comb,
                          bl_gp, bl_sp, nullptr, nullptr,
                          out_hpf, pf_h, NPF, NPF, 3, 0);
    GemmJob gSW1 = mkGemm(mean_sw, x_sw, nullptr, Wl_ps, Wr_ps, nullptr,
                          bl_ps, nullptr, W_sw, b_sw,
                          out_sw, 0, sw_h, NSW, 2, 1);
    GemmJob gSW2 = mkGemm(mean_sw, x_sw, nullptr, Wl_ps, Wr_ps, nullptr,
                          bl_ps, nullptr, W_sw, b_sw,
                          out_sw, sw_h, NSW, NSW, 2, 1);
    GemmJob gGW[5];
    for (int i = 0; i < 5; i++)
        gGW[i] = mkGemm(mean_gw, x_gw, nullptr, Wl_pg, Wr_pg, nullptr,
                        bl_pg, nullptr, W_gw, b_gw,
                        out_gw, gg[i], gg[i + 1], NGW, 2, 1);

    // P0: agg gp1 + sp1 (no gemm ready yet)
    launch(GZ, GZ, aGP1, aSP1, AZ);
    // P1: gemm pf1 (80 blk)          || agg gp2, sp2, sw1
    launch(gPF1, GZ, aGP2, aSP2, aSW1);
    // P2: gemm pf2 + sw1 (157 blk)   || agg sw2, gw slice 0
    launch(gPF2, gSW1, aSW2, aGW[0], AZ);
    // P3: gemm sw2 (155 blk)         || agg gw slice 1
    launch(gSW2, GZ, aGW[1], AZ, AZ);
    // P4: gemm gw0 (156 blk)         || agg gw slice 2
    launch(gGW[0], GZ, aGW[2], AZ, AZ);
    // P5: gemm gw1 (156 blk)         || agg gw slice 3
    launch(gGW[1], GZ, aGW[3], AZ, AZ);
    // P6: gemm gw2 (156 blk)         || agg gw slice 4
    launch(gGW[2], GZ, aGW[4], AZ, AZ);
    // P7: gemm gw3
    launch(gGW[3], GZ, AZ, AZ, AZ);
    // P8: gemm gw4
    launch(gGW[4], GZ, AZ, AZ, AZ);

    (void)n_in; (void)out_size; (void)in_sizes;
}

// round 14
// speedup vs baseline: 1.4504x; 1.4504x over previous
#include <cuda_runtime.h>
#include <cuda_bf16.h>
#include <cstdint>

// ---------------------------------------------------------------------------
// Problem constants
// ---------------------------------------------------------------------------
#define NPF 20000
#define NGW 100000
#define NSW 30000
#define D   128

#define EPG 1600000
#define EGP 640000
#define EPS 480000
#define ESP 320000
#define ETOT (EPG + EGP + EPS + ESP)

#define NTOT (NGW + NPF + NSW + NPF)

// ---------------------------------------------------------------------------
// Device scratch (no allocations allowed -> __device__ globals)
// ---------------------------------------------------------------------------
__device__ float g_mean_gw[(size_t)NGW * D];
__device__ float g_mean_sw[(size_t)NSW * D];
__device__ float g_mean_gp[(size_t)NPF * D];
__device__ float g_mean_sp[(size_t)NPF * D];
__device__ int   g_cnt[NTOT];
__device__ int   g_rowptr[NTOT];
__device__ int   g_cursor[NTOT];
__device__ int   g_perm[ETOT];
__device__ int   g_partials[4 * 128];
__device__ float g_wr_comb[D * D];
// bf16 copies of the feature tables (gather sources only)
__device__ __nv_bfloat16 g_xb_pfas[(size_t)NPF * D];
__device__ __nv_bfloat16 g_xb_gw[(size_t)NGW * D];
__device__ __nv_bfloat16 g_xb_sw[(size_t)NSW * D];

// ---------------------------------------------------------------------------
// small utility kernels
// ---------------------------------------------------------------------------
__global__ void zero_int_kernel(int* __restrict__ p, int n4) {
    int i = blockIdx.x * blockDim.x + threadIdx.x;
    if (i < n4) reinterpret_cast<int4*>(p)[i] = make_int4(0, 0, 0, 0);
}

__global__ void addw_kernel(const float* __restrict__ a, const float* __restrict__ b,
                            float* __restrict__ o) {
    int i = blockIdx.x * blockDim.x + threadIdx.x;
    if (i < D * D) o[i] = a[i] + b[i];
}

// fp32 -> bf16 table conversion (4 elements per thread)
__global__ void conv_bf16_kernel(const float* __restrict__ x,
                                 __nv_bfloat16* __restrict__ y, int n4) {
    int i = blockIdx.x * blockDim.x + threadIdx.x;
    if (i >= n4) return;
    float4 v = reinterpret_cast<const float4*>(x)[i];
    __nv_bfloat162 a = __floats2bfloat162_rn(v.x, v.y);
    __nv_bfloat162 b = __floats2bfloat162_rn(v.z, v.w);
    uint2 p;
    p.x = *reinterpret_cast<unsigned*>(&a);
    p.y = *reinterpret_cast<unsigned*>(&b);
    reinterpret_cast<uint2*>(y)[i] = p;
}

// ---------------------------------------------------------------------------
// CSR build: histogram -> scan -> permutation (per relation)
// ---------------------------------------------------------------------------
__global__ void hist_kernel(const int* __restrict__ dst, int* __restrict__ cnt, int E) {
    int e = blockIdx.x * blockDim.x + threadIdx.x;
    if (e < E) atomicAdd(&cnt[dst[e]], 1);
}

__global__ void scan_reduce_kernel(const int* __restrict__ cnt, int n,
                                   int* __restrict__ partials) {
    __shared__ int s[256];
    int t = threadIdx.x;
    int base = blockIdx.x * 1024 + t * 4;
    int sum = 0;
#pragma unroll
    for (int j = 0; j < 4; j++) {
        int idx = base + j;
        if (idx < n) sum += cnt[idx];
    }
    s[t] = sum;
    __syncthreads();
    for (int off = 128; off > 0; off >>= 1) {
        if (t < off) s[t] += s[t + off];
        __syncthreads();
    }
    if (t == 0) partials[blockIdx.x] = s[0];
}

// parallel exclusive scan of <=128 partials
__global__ void scan_partials_kernel(int* __restrict__ partials, int nb) {
    __shared__ int s[128];
    int t = threadIdx.x;
    int v = (t < nb) ? partials[t] : 0;
    s[t] = v;
    __syncthreads();
    for (int off = 1; off < 128; off <<= 1) {
        int y = (t >= off) ? s[t - off] : 0;
        __syncthreads();
        s[t] += y;
        __syncthreads();
    }
    if (t < nb) partials[t] = s[t] - v;
}

__global__ void scan_write_kernel(const int* __restrict__ cnt, int n,
                                  const int* __restrict__ partials,
                                  int* __restrict__ rowptr,
                                  int* __restrict__ cursor) {
    __shared__ int wsum[8];
    __shared__ int woff[8];
    int t = threadIdx.x;
    int lane = t & 31, warp = t >> 5;
    int base = blockIdx.x * 1024 + t * 4;
    int v[4];
    int tsum = 0;
#pragma unroll
    for (int j = 0; j < 4; j++) {
        int idx = base + j;
        v[j] = (idx < n) ? cnt[idx] : 0;
        tsum += v[j];
    }
    int incl = tsum;
#pragma unroll
    for (int o = 1; o < 32; o <<= 1) {
        int y = __shfl_up_sync(0xffffffffu, incl, o);
        if (lane >= o) incl += y;
    }
    int excl = incl - tsum;
    if (lane == 31) wsum[warp] = incl;
    __syncthreads();
    if (t == 0) {
        int r = 0;
        for (int i = 0; i < 8; i++) { woff[i] = r; r += wsum[i]; }
    }
    __syncthreads();
    int run = partials[blockIdx.x] + woff[warp] + excl;
#pragma unroll
    for (int j = 0; j < 4; j++) {
        int idx = base + j;
        if (idx < n) { rowptr[idx] = run; cursor[idx] = run; run += v[j]; }
    }
}

__global__ void permute_kernel(const int* __restrict__ src, const int* __restrict__ dst,
                               int* __restrict__ cursor, int* __restrict__ perm, int E) {
    int e = blockIdx.x * blockDim.x + threadIdx.x;
    if (e < E) {
        int pos = atomicAdd(&cursor[dst[e]], 1);
        perm[pos] = src[e];
    }
}

// ---------------------------------------------------------------------------
// Pull aggregation from bf16 tables: one warp per destination node.
// Each lane covers 4 features (8B loads). 8-edge batching for MLP.
// fp32 accumulate, fp32 mean output.
// ---------------------------------------------------------------------------
__global__ __launch_bounds__(256) void aggregate_kernel(
    const __nv_bfloat16* __restrict__ xb,
    const int*   __restrict__ rowptr,
    const int*   __restrict__ perm,
    float* __restrict__ outmean,
    int N, int E)
{
    int w = (blockIdx.x * blockDim.x + threadIdx.x) >> 5;
    int lane = threadIdx.x & 31;
    if (w >= N) return;

    int start = rowptr[w];
    int end   = (w + 1 < N) ? rowptr[w + 1] : E;

    float4 acc = make_float4(0.f, 0.f, 0.f, 0.f);
    for (int e0 = start; e0 < end; e0 += 32) {
        int idx = (e0 + lane < end) ? perm[e0 + lane] : 0;
        int m = min(32, end - e0);
        int j = 0;
        for (; j + 8 <= m; j += 8) {
            uint2 u[8];
#pragma unroll
            for (int q = 0; q < 8; q++) {
                int s = __shfl_sync(0xffffffffu, idx, j + q);
                u[q] = *reinterpret_cast<const uint2*>(xb + (size_t)s * D + lane * 4);
            }
#pragma unroll
            for (int q = 0; q < 8; q++) {
                float2 lo = __bfloat1622float2(*reinterpret_cast<__nv_bfloat162*>(&u[q].x));
                float2 hi = __bfloat1622float2(*reinterpret_cast<__nv_bfloat162*>(&u[q].y));
                acc.x += lo.x; acc.y += lo.y; acc.z += hi.x; acc.w += hi.y;
            }
        }
        for (; j < m; j++) {
            int s = __shfl_sync(0xffffffffu, idx, j);
            uint2 u = *reinterpret_cast<const uint2*>(xb + (size_t)s * D + lane * 4);
            float2 lo = __bfloat1622float2(*reinterpret_cast<__nv_bfloat162*>(&u.x));
            float2 hi = __bfloat1622float2(*reinterpret_cast<__nv_bfloat162*>(&u.y));
            acc.x += lo.x; acc.y += lo.y; acc.z += hi.x; acc.w += hi.y;
        }
    }
    float inv = 1.0f / fmaxf((float)(end - start), 1.0f);
    acc.x *= inv; acc.y *= inv; acc.z *= inv; acc.w *= inv;
    *reinterpret_cast<float4*>(outmean + (size_t)w * D + lane * 4) = acc;
}

// ---------------------------------------------------------------------------
// Fused GEMM with packed f32x2 FMA (exact R3/R7 structure):
//   h[row, :] = sum_seg A_seg[row, :] @ W_seg + bias1 (+ bias2)
//   MODE 0: out[row*128 + c] = relu(h)
//   MODE 1: out[row] = relu(h) . whead + bhead
// ---------------------------------------------------------------------------
template<int NSEG, int MODE>
__global__ __launch_bounds__(256) void gemm_fused(
    const float* __restrict__ A0, const float* __restrict__ A1,
    const float* __restrict__ A2,
    const float* __restrict__ W0, const float* __restrict__ W1,
    const float* __restrict__ W2,
    const float* __restrict__ bias1, const float* __restrict__ bias2,
    const float* __restrict__ whead, const float* __restrict__ bhead,
    float* __restrict__ out, int n_rows)
{
    constexpr int KC  = 16;
    constexpr int LDT = 132;
    __shared__ float As[KC][LDT];
    __shared__ float Ws[KC][LDT];
    __shared__ float red[128];

    const int t    = threadIdx.x;
    const int row0 = blockIdx.x * 128;
    const int trow = t >> 4;
    const int tcol = t & 15;

    const float* Aseg[3] = {A0, A1, A2};
    const float* Wseg[3] = {W0, W1, W2};

    unsigned long long accp[8][4];
#pragma unroll
    for (int i = 0; i < 8; i++)
#pragma unroll
        for (int j2 = 0; j2 < 4; j2++) accp[i][j2] = 0ull;

    const int nchunks = NSEG * D / KC;
    for (int ch = 0; ch < nchunks; ch++) {
        const int k0   = ch * KC;
        const int seg  = k0 / D;
        const int kin0 = k0 % D;
        const float* A = Aseg[seg];
        const float* W = Wseg[seg];

#pragma unroll
        for (int it = 0; it < 2; it++) {
            int idx  = t + it * 256;
            int row  = idx >> 2;
            int q    = idx & 3;
            int grow = row0 + row;
            float4 v = make_float4(0.f, 0.f, 0.f, 0.f);
            if (grow < n_rows)
                v = *reinterpret_cast<const float4*>(A + (size_t)grow * D + kin0 + q * 4);
            As[q * 4 + 0][row] = v.x;
            As[q * 4 + 1][row] = v.y;
            As[q * 4 + 2][row] = v.z;
            As[q * 4 + 3][row] = v.w;
        }
#pragma unroll
        for (int it = 0; it < 2; it++) {
            int idx = t + it * 256;
            int kk  = idx >> 5;
            int cq  = idx & 31;
            float4 w = *reinterpret_cast<const float4*>(W + (size_t)(kin0 + kk) * D + cq * 4);
            *reinterpret_cast<float4*>(&Ws[kk][cq * 4]) = w;
        }
        __syncthreads();

#pragma unroll
        for (int kk = 0; kk < KC; kk++) {
            float4 a0 = *reinterpret_cast<const float4*>(&As[kk][trow * 4]);
            float4 a1 = *reinterpret_cast<const float4*>(&As[kk][64 + trow * 4]);
            unsigned long long wp[4];
            wp[0] = *reinterpret_cast<const unsigned long long*>(&Ws[kk][tcol * 4]);
            wp[1] = *reinterpret_cast<const unsigned long long*>(&Ws[kk][tcol * 4 + 2]);
            wp[2] = *reinterpret_cast<const unsigned long long*>(&Ws[kk][64 + tcol * 4]);
            wp[3] = *reinterpret_cast<const unsigned long long*>(&Ws[kk][64 + tcol * 4 + 2]);
            float a[8] = {a0.x, a0.y, a0.z, a0.w, a1.x, a1.y, a1.z, a1.w};
#pragma unroll
            for (int i = 0; i < 8; i++) {
                unsigned long long ap;
                asm("mov.b64 %0, {%1, %1};" : "=l"(ap) : "f"(a[i]));
#pragma unroll
                for (int j2 = 0; j2 < 4; j2++)
                    asm("fma.rn.f32x2 %0, %1, %2, %0;"
                        : "+l"(accp[i][j2]) : "l"(ap), "l"(wp[j2]));
            }
        }
        __syncthreads();
    }

    float acc[8][8];
#pragma unroll
    for (int i = 0; i < 8; i++)
#pragma unroll
        for (int j2 = 0; j2 < 4; j2++)
            asm("mov.b64 {%0, %1}, %2;"
                : "=f"(acc[i][2 * j2]), "=f"(acc[i][2 * j2 + 1]) : "l"(accp[i][j2]));

    int cidx[8], ridx[8];
#pragma unroll
    for (int j = 0; j < 8; j++)
        cidx[j] = (j < 4) ? (tcol * 4 + j) : (64 + tcol * 4 + (j - 4));
#pragma unroll
    for (int i = 0; i < 8; i++)
        ridx[i] = (i < 4) ? (trow * 4 + i) : (64 + trow * 4 + (i - 4));

    float b[8];
#pragma unroll
    for (int j = 0; j < 8; j++)
        b[j] = bias1[cidx[j]] + (bias2 ? bias2[cidx[j]] : 0.f);

    if (MODE == 0) {
#pragma unroll
        for (int i = 0; i < 8; i++) {
            int grow = row0 + ridx[i];
            if (grow < n_rows) {
#pragma unroll
                for (int j = 0; j < 8; j++)
                    out[(size_t)grow * D + cidx[j]] = fmaxf(acc[i][j] + b[j], 0.f);
            }
        }
    } else {
        float wh[8];
#pragma unroll
        for (int j = 0; j < 8; j++) wh[j] = whead[cidx[j]];
        if (t < 128) red[t] = 0.f;
        __syncthreads();
#pragma unroll
        for (int i = 0; i < 8; i++) {
            float partial = 0.f;
#pragma unroll
            for (int j = 0; j < 8; j++)
                partial += fmaxf(acc[i][j] + b[j], 0.f) * wh[j];
            atomicAdd(&red[ridx[i]], partial);
        }
        __syncthreads();
        if (t < 128) {
            int grow = row0 + t;
            if (grow < n_rows) out[grow] = red[t] + bhead[0];
        }
    }
}

// ---------------------------------------------------------------------------
// Launch: R7's proven 3-branch fork (2 extra streams + 3 events).
// ---------------------------------------------------------------------------
extern "C" void kernel_launch(void* const* d_in, const int* in_sizes, int n_in,
                              void* d_out, int out_size)
{
    const float* x_pfas = (const float*)d_in[0];
    const float* x_gw   = (const float*)d_in[1];
    const float* x_sw   = (const float*)d_in[2];
    const int* ei_pg_src = (const int*)d_in[3];
    const int* ei_pg_dst = (const int*)d_in[4];
    const int* ei_gp_src = (const int*)d_in[5];
    const int* ei_gp_dst = (const int*)d_in[6];
    const int* ei_ps_src = (const int*)d_in[7];
    const int* ei_ps_dst = (const int*)d_in[8];
    const int* ei_sp_src = (const int*)d_in[9];
    const int* ei_sp_dst = (const int*)d_in[10];
    const float* Wl_pg = (const float*)d_in[11];
    const float* bl_pg = (const float*)d_in[12];
    const float* Wr_pg = (const float*)d_in[13];
    const float* Wl_gp = (const float*)d_in[14];
    const float* bl_gp = (const float*)d_in[15];
    const float* Wr_gp = (const float*)d_in[16];
    const float* Wl_ps = (const float*)d_in[17];
    const float* bl_ps = (const float*)d_in[18];
    const float* Wr_ps = (const float*)d_in[19];
    const float* Wl_sp = (const float*)d_in[20];
    const float* bl_sp = (const float*)d_in[21];
    const float* Wr_sp = (const float*)d_in[22];
    const float* W_gw  = (const float*)d_in[23];
    const float* b_gw  = (const float*)d_in[24];
    const float* W_sw  = (const float*)d_in[25];
    const float* b_sw  = (const float*)d_in[26];

    const int E_PG = in_sizes[3];
    const int E_GP = in_sizes[5];
    const int E_PS = in_sizes[7];
    const int E_SP = in_sizes[9];

    float* out = (float*)d_out;
    float* out_hpf = out;                       // [20000, 128]
    float* out_gw  = out + (size_t)NPF * D;     // [100000]
    float* out_sw  = out_gw + NGW;              // [30000]

    static float *mean_gw = nullptr, *mean_sw = nullptr, *mean_gp = nullptr, *mean_sp = nullptr;
    static float *wr_comb = nullptr;
    static int *cnt = nullptr, *rowptr = nullptr, *cursor = nullptr, *perm = nullptr, *partials = nullptr;
    static __nv_bfloat16 *xb_pfas = nullptr, *xb_gw = nullptr, *xb_sw = nullptr;
    static cudaStream_t s1 = nullptr, s2 = nullptr;
    static cudaEvent_t evRoot = nullptr, ev1 = nullptr, ev2 = nullptr;
    if (!mean_gw) {
        cudaGetSymbolAddress((void**)&mean_gw, g_mean_gw);
        cudaGetSymbolAddress((void**)&mean_sw, g_mean_sw);
        cudaGetSymbolAddress((void**)&mean_gp, g_mean_gp);
        cudaGetSymbolAddress((void**)&mean_sp, g_mean_sp);
        cudaGetSymbolAddress((void**)&wr_comb, g_wr_comb);
        cudaGetSymbolAddress((void**)&cnt, g_cnt);
        cudaGetSymbolAddress((void**)&rowptr, g_rowptr);
        cudaGetSymbolAddress((void**)&cursor, g_cursor);
        cudaGetSymbolAddress((void**)&perm, g_perm);
        cudaGetSymbolAddress((void**)&partials, g_partials);
        cudaGetSymbolAddress((void**)&xb_pfas, g_xb_pfas);
        cudaGetSymbolAddress((void**)&xb_gw, g_xb_gw);
        cudaGetSymbolAddress((void**)&xb_sw, g_xb_sw);
        cudaStreamCreateWithFlags(&s1, cudaStreamNonBlocking);
        cudaStreamCreateWithFlags(&s2, cudaStreamNonBlocking);
        cudaEventCreateWithFlags(&evRoot, cudaEventDisableTiming);
        cudaEventCreateWithFlags(&ev1, cudaEventDisableTiming);
        cudaEventCreateWithFlags(&ev2, cudaEventDisableTiming);
    }

    const int off_pg = 0;
    const int off_gp = NGW;
    const int off_ps = NGW + NPF;
    const int off_sp = NGW + NPF + NSW;
    const int poff_pg = 0;
    const int poff_gp = E_PG;
    const int poff_ps = E_PG + E_GP;
    const int poff_sp = E_PG + E_GP + E_PS;

    // ---- root: zero counters + convert pfas table (needed by s1 & s2) ----
    zero_int_kernel<<<(NTOT / 4 + 255) / 256, 256>>>(cnt, NTOT / 4);
    conv_bf16_kernel<<<((NPF * D / 4) + 255) / 256, 256>>>(x_pfas, xb_pfas, NPF * D / 4);
    cudaEventRecord(evRoot, 0);
    cudaStreamWaitEvent(s1, evRoot, 0);
    cudaStreamWaitEvent(s2, evRoot, 0);

    // ================= Branch 1 (stream s1): gw head chain (largest) ========
    {
        hist_kernel<<<(E_PG + 255) / 256, 256, 0, s1>>>(ei_pg_dst, cnt + off_pg, E_PG);
        int nb = (NGW + 1023) / 1024;
        scan_reduce_kernel<<<nb, 256, 0, s1>>>(cnt + off_pg, NGW, partials + 0 * 128);
        scan_partials_kernel<<<1, 128, 0, s1>>>(partials + 0 * 128, nb);
        scan_write_kernel<<<nb, 256, 0, s1>>>(cnt + off_pg, NGW, partials + 0 * 128,
                                              rowptr + off_pg, cursor + off_pg);
        permute_kernel<<<(E_PG + 255) / 256, 256, 0, s1>>>(
            ei_pg_src, ei_pg_dst, cursor + off_pg, perm + poff_pg, E_PG);
        aggregate_kernel<<<(NGW + 7) / 8, 256, 0, s1>>>(
            xb_pfas, rowptr + off_pg, perm + poff_pg, mean_gw, NGW, E_PG);
        gemm_fused<2, 1><<<(NGW + 127) / 128, 256, 0, s1>>>(
            mean_gw, x_gw, nullptr,
            Wl_pg, Wr_pg, nullptr,
            bl_pg, nullptr, W_gw, b_gw,
            out_gw, NGW);
    }

    // ================= Branch 2 (stream s2): sw head chain ==================
    {
        hist_kernel<<<(E_PS + 255) / 256, 256, 0, s2>>>(ei_ps_dst, cnt + off_ps, E_PS);
        int nb = (NSW + 1023) / 1024;
        scan_reduce_kernel<<<nb, 256, 0, s2>>>(cnt + off_ps, NSW, partials + 2 * 128);
        scan_partials_kernel<<<1, 128, 0, s2>>>(partials + 2 * 128, nb);
        scan_write_kernel<<<nb, 256, 0, s2>>>(cnt + off_ps, NSW, partials + 2 * 128,
                                              rowptr + off_ps, cursor + off_ps);
        permute_kernel<<<(E_PS + 255) / 256, 256, 0, s2>>>(
            ei_ps_src, ei_ps_dst, cursor + off_ps, perm + poff_ps, E_PS);
        aggregate_kernel<<<(NSW + 7) / 8, 256, 0, s2>>>(
            xb_pfas, rowptr + off_ps, perm + poff_ps, mean_sw, NSW, E_PS);
        gemm_fused<2, 1><<<(NSW + 127) / 128, 256, 0, s2>>>(
            mean_sw, x_sw, nullptr,
            Wl_ps, Wr_ps, nullptr,
            bl_ps, nullptr, W_sw, b_sw,
            out_sw, NSW);
    }

    // ================= Branch 0 (origin stream): pfas chain =================
    {
        conv_bf16_kernel<<<((NGW * D / 4) + 255) / 256, 256>>>(x_gw, xb_gw, NGW * D / 4);
        conv_bf16_kernel<<<((NSW * D / 4) + 255) / 256, 256>>>(x_sw, xb_sw, NSW * D / 4);
        addw_kernel<<<(D * D + 255) / 256, 256>>>(Wr_gp, Wr_sp, wr_comb);
        hist_kernel<<<(E_GP + 255) / 256, 256>>>(ei_gp_dst, cnt + off_gp, E_GP);
        hist_kernel<<<(E_SP + 255) / 256, 256>>>(ei_sp_dst, cnt + off_sp, E_SP);
        int nb = (NPF + 1023) / 1024;
        scan_reduce_kernel<<<nb, 256>>>(cnt + off_gp, NPF, partials + 1 * 128);
        scan_partials_kernel<<<1, 128>>>(partials + 1 * 128, nb);
        scan_write_kernel<<<nb, 256>>>(cnt + off_gp, NPF, partials + 1 * 128,
                                       rowptr + off_gp, cursor + off_gp);
        scan_reduce_kernel<<<nb, 256>>>(cnt + off_sp, NPF, partials + 3 * 128);
        scan_partials_kernel<<<1, 128>>>(partials + 3 * 128, nb);
        scan_write_kernel<<<nb, 256>>>(cnt + off_sp, NPF, partials + 3 * 128,
                                       rowptr + off_sp, cursor + off_sp);
        permute_kernel<<<(E_GP + 255) / 256, 256>>>(
            ei_gp_src, ei_gp_dst, cursor + off_gp, perm + poff_gp, E_GP);
        permute_kernel<<<(E_SP + 255) / 256, 256>>>(
            ei_sp_src, ei_sp_dst, cursor + off_sp, perm + poff_sp, E_SP);
        aggregate_kernel<<<(NPF + 7) / 8, 256>>>(
            xb_gw, rowptr + off_gp, perm + poff_gp, mean_gp, NPF, E_GP);
        aggregate_kernel<<<(NPF + 7) / 8, 256>>>(
            xb_sw, rowptr + off_sp, perm + poff_sp, mean_sp, NPF, E_SP);
        gemm_fused<3, 0><<<(NPF + 127) / 128, 256>>>(
            mean_gp, mean_sp, x_pfas,
            Wl_gp, Wl_sp, wr_comb,
            bl_gp, bl_sp, nullptr, nullptr,
            out_hpf, NPF);
    }

    // ---- join branches back to the origin stream ----
    cudaEventRecord(ev1, s1);
    cudaEventRecord(ev2, s2);
    cudaStreamWaitEvent(0, ev1, 0);
    cudaStreamWaitEvent(0, ev2, 0);

    (void)n_in; (void)out_size;
}

// round 15
// speedup vs baseline: 1.4805x; 1.0208x over previous
#include <cuda_runtime.h>
#include <cuda_bf16.h>
#include <cstdint>

// ---------------------------------------------------------------------------
// Problem constants
// ---------------------------------------------------------------------------
#define NPF 20000
#define NGW 100000
#define NSW 30000
#define D   128

#define EPG 1600000
#define EGP 640000
#define EPS 480000
#define ESP 320000
#define ETOT (EPG + EGP + EPS + ESP)

#define NTOT (NGW + NPF + NSW + NPF)

// ---------------------------------------------------------------------------
// Device scratch (no allocations allowed -> __device__ globals)
// ---------------------------------------------------------------------------
__device__ float g_mean_gw[(size_t)NGW * D];
__device__ float g_mean_sw[(size_t)NSW * D];
__device__ float g_mean_gp[(size_t)NPF * D];
__device__ float g_mean_sp[(size_t)NPF * D];
__device__ int   g_cnt[NTOT];
__device__ int   g_rowptr[NTOT];
__device__ int   g_cursor[NTOT];
__device__ int   g_perm[ETOT];
__device__ int   g_partials[4 * 128];
__device__ float g_wr_comb[D * D];

// ---------------------------------------------------------------------------
// small utility kernels
// ---------------------------------------------------------------------------
__global__ void zero_int_kernel(int* __restrict__ p, int n4) {
    int i = blockIdx.x * blockDim.x + threadIdx.x;
    if (i < n4) reinterpret_cast<int4*>(p)[i] = make_int4(0, 0, 0, 0);
}

__global__ void addw_kernel(const float* __restrict__ a, const float* __restrict__ b,
                            float* __restrict__ o) {
    int i = blockIdx.x * blockDim.x + threadIdx.x;
    if (i < D * D) o[i] = a[i] + b[i];
}

// ---------------------------------------------------------------------------
// CSR build: histogram -> scan -> permutation (per relation)
// ---------------------------------------------------------------------------
__global__ void hist_kernel(const int* __restrict__ dst, int* __restrict__ cnt, int E) {
    int e = blockIdx.x * blockDim.x + threadIdx.x;
    if (e < E) atomicAdd(&cnt[dst[e]], 1);
}

__global__ void scan_reduce_kernel(const int* __restrict__ cnt, int n,
                                   int* __restrict__ partials) {
    __shared__ int s[256];
    int t = threadIdx.x;
    int base = blockIdx.x * 1024 + t * 4;
    int sum = 0;
#pragma unroll
    for (int j = 0; j < 4; j++) {
        int idx = base + j;
        if (idx < n) sum += cnt[idx];
    }
    s[t] = sum;
    __syncthreads();
    for (int off = 128; off > 0; off >>= 1) {
        if (t < off) s[t] += s[t + off];
        __syncthreads();
    }
    if (t == 0) partials[blockIdx.x] = s[0];
}

// parallel exclusive scan of <=128 partials
__global__ void scan_partials_kernel(int* __restrict__ partials, int nb) {
    __shared__ int s[128];
    int t = threadIdx.x;
    int v = (t < nb) ? partials[t] : 0;
    s[t] = v;
    __syncthreads();
    for (int off = 1; off < 128; off <<= 1) {
        int y = (t >= off) ? s[t - off] : 0;
        __syncthreads();
        s[t] += y;
        __syncthreads();
    }
    if (t < nb) partials[t] = s[t] - v;
}

__global__ void scan_write_kernel(const int* __restrict__ cnt, int n,
                                  const int* __restrict__ partials,
                                  int* __restrict__ rowptr,
                                  int* __restrict__ cursor) {
    __shared__ int wsum[8];
    __shared__ int woff[8];
    int t = threadIdx.x;
    int lane = t & 31, warp = t >> 5;
    int base = blockIdx.x * 1024 + t * 4;
    int v[4];
    int tsum = 0;
#pragma unroll
    for (int j = 0; j < 4; j++) {
        int idx = base + j;
        v[j] = (idx < n) ? cnt[idx] : 0;
        tsum += v[j];
    }
    int incl = tsum;
#pragma unroll
    for (int o = 1; o < 32; o <<= 1) {
        int y = __shfl_up_sync(0xffffffffu, incl, o);
        if (lane >= o) incl += y;
    }
    int excl = incl - tsum;
    if (lane == 31) wsum[warp] = incl;
    __syncthreads();
    if (t == 0) {
        int r = 0;
        for (int i = 0; i < 8; i++) { woff[i] = r; r += wsum[i]; }
    }
    __syncthreads();
    int run = partials[blockIdx.x] + woff[warp] + excl;
#pragma unroll
    for (int j = 0; j < 4; j++) {
        int idx = base + j;
        if (idx < n) { rowptr[idx] = run; cursor[idx] = run; run += v[j]; }
    }
}

__global__ void permute_kernel(const int* __restrict__ src, const int* __restrict__ dst,
                               int* __restrict__ cursor, int* __restrict__ perm, int E) {
    int e = blockIdx.x * blockDim.x + threadIdx.x;
    if (e < E) {
        int pos = atomicAdd(&cursor[dst[e]], 1);
        perm[pos] = src[e];
    }
}

// ---------------------------------------------------------------------------
// Pull aggregation (fp32, proven): one warp per destination node,
// 4-edge batching.
// ---------------------------------------------------------------------------
__global__ __launch_bounds__(256) void aggregate_kernel(
    const float* __restrict__ x,
    const int*   __restrict__ rowptr,
    const int*   __restrict__ perm,
    float* __restrict__ outmean,
    int N, int E)
{
    int w = (blockIdx.x * blockDim.x + threadIdx.x) >> 5;
    int lane = threadIdx.x & 31;
    if (w >= N) return;

    int start = rowptr[w];
    int end   = (w + 1 < N) ? rowptr[w + 1] : E;

    float4 acc = make_float4(0.f, 0.f, 0.f, 0.f);
    for (int e0 = start; e0 < end; e0 += 32) {
        int idx = (e0 + lane < end) ? perm[e0 + lane] : 0;
        int m = min(32, end - e0);
        int j = 0;
        for (; j + 4 <= m; j += 4) {
            int s0 = __shfl_sync(0xffffffffu, idx, j + 0);
            int s1 = __shfl_sync(0xffffffffu, idx, j + 1);
            int s2 = __shfl_sync(0xffffffffu, idx, j + 2);
            int s3 = __shfl_sync(0xffffffffu, idx, j + 3);
            float4 v0 = *reinterpret_cast<const float4*>(x + (size_t)s0 * D + lane * 4);
            float4 v1 = *reinterpret_cast<const float4*>(x + (size_t)s1 * D + lane * 4);
            float4 v2 = *reinterpret_cast<const float4*>(x + (size_t)s2 * D + lane * 4);
            float4 v3 = *reinterpret_cast<const float4*>(x + (size_t)s3 * D + lane * 4);
            acc.x += (v0.x + v1.x) + (v2.x + v3.x);
            acc.y += (v0.y + v1.y) + (v2.y + v3.y);
            acc.z += (v0.z + v1.z) + (v2.z + v3.z);
            acc.w += (v0.w + v1.w) + (v2.w + v3.w);
        }
        for (; j < m; j++) {
            int s = __shfl_sync(0xffffffffu, idx, j);
            float4 v = *reinterpret_cast<const float4*>(x + (size_t)s * D + lane * 4);
            acc.x += v.x; acc.y += v.y; acc.z += v.z; acc.w += v.w;
        }
    }
    float inv = 1.0f / fmaxf((float)(end - start), 1.0f);
    acc.x *= inv; acc.y *= inv; acc.z *= inv; acc.w *= inv;
    *reinterpret_cast<float4*>(outmean + (size_t)w * D + lane * 4) = acc;
}

// ---------------------------------------------------------------------------
// Fused GEMM, f32x2 packed, DOUBLE-BUFFERED staging:
//   one __syncthreads per K-chunk; next chunk's gmem loads are issued before
//   compute so LDG latency hides under the FFMA2 stream.
//   h[row, :] = sum_seg A_seg[row, :] @ W_seg + bias1 (+ bias2)
//   MODE 0: out[row*128 + c] = relu(h)
//   MODE 1: out[row] = relu(h) . whead + bhead
// ---------------------------------------------------------------------------
template<int NSEG, int MODE>
__global__ __launch_bounds__(256) void gemm_fused(
    const float* __restrict__ A0, const float* __restrict__ A1,
    const float* __restrict__ A2,
    const float* __restrict__ W0, const float* __restrict__ W1,
    const float* __restrict__ W2,
    const float* __restrict__ bias1, const float* __restrict__ bias2,
    const float* __restrict__ whead, const float* __restrict__ bhead,
    float* __restrict__ out, int n_rows)
{
    constexpr int KC  = 16;
    constexpr int LDT = 132;
    __shared__ float As[2][KC][LDT];
    __shared__ float Ws[2][KC][LDT];
    __shared__ float red[128];

    const int t    = threadIdx.x;
    const int row0 = blockIdx.x * 128;
    const int trow = t >> 4;
    const int tcol = t & 15;

    const float* Aseg[3] = {A0, A1, A2};
    const float* Wseg[3] = {W0, W1, W2};

    // per-thread staging indices (constant across chunks)
    const int a_row = t >> 1;             // 0..127  (two threads per row)
    const int a_q   = (t & 1) * 2;        // quad pair base: 0 or 2
    const int w_kk  = t >> 4;             // 0..15
    const int w_cq  = t & 15;             // 0..15 (16B groups, x2 iterations)

    unsigned long long accp[8][4];
#pragma unroll
    for (int i = 0; i < 8; i++)
#pragma unroll
        for (int j2 = 0; j2 < 4; j2++) accp[i][j2] = 0ull;

    const int nchunks = NSEG * D / KC;

    // prefetch registers: 2 float4 of A (two quads of one row), 2 float4 of W
    float4 pa0, pa1, pw0, pw1;

    auto prefetch = [&](int ch) {
        const int k0   = ch * KC;
        const int seg  = k0 / D;
        const int kin0 = k0 % D;
        const float* A = Aseg[seg];
        const float* W = Wseg[seg];
        int grow = row0 + a_row;
        if (grow < n_rows) {
            pa0 = *reinterpret_cast<const float4*>(A + (size_t)grow * D + kin0 + a_q * 4);
            pa1 = *reinterpret_cast<const float4*>(A + (size_t)grow * D + kin0 + (a_q + 1) * 4);
        } else {
            pa0 = make_float4(0.f, 0.f, 0.f, 0.f);
            pa1 = make_float4(0.f, 0.f, 0.f, 0.f);
        }
        pw0 = *reinterpret_cast<const float4*>(W + (size_t)(kin0 + w_kk) * D + w_cq * 4);
        pw1 = *reinterpret_cast<const float4*>(W + (size_t)(kin0 + w_kk) * D + (w_cq + 16) * 4);
    };

    auto store_stage = [&](int b) {
        As[b][a_q * 4 + 0][a_row] = pa0.x;
        As[b][a_q * 4 + 1][a_row] = pa0.y;
        As[b][a_q * 4 + 2][a_row] = pa0.z;
        As[b][a_q * 4 + 3][a_row] = pa0.w;
        As[b][a_q * 4 + 4][a_row] = pa1.x;
        As[b][a_q * 4 + 5][a_row] = pa1.y;
        As[b][a_q * 4 + 6][a_row] = pa1.z;
        As[b][a_q * 4 + 7][a_row] = pa1.w;
        *reinterpret_cast<float4*>(&Ws[b][w_kk][w_cq * 4]) = pw0;
        *reinterpret_cast<float4*>(&Ws[b][w_kk][(w_cq + 16) * 4]) = pw1;
    };

    prefetch(0);

    for (int ch = 0; ch < nchunks; ch++) {
        const int b = ch & 1;
        store_stage(b);
        __syncthreads();
        if (ch + 1 < nchunks) prefetch(ch + 1);   // LDG latency hides under compute

#pragma unroll
        for (int kk = 0; kk < KC; kk++) {
            float4 a0 = *reinterpret_cast<const float4*>(&As[b][kk][trow * 4]);
            float4 a1 = *reinterpret_cast<const float4*>(&As[b][kk][64 + trow * 4]);
            unsigned long long wp[4];
            wp[0] = *reinterpret_cast<const unsigned long long*>(&Ws[b][kk][tcol * 4]);
            wp[1] = *reinterpret_cast<const unsigned long long*>(&Ws[b][kk][tcol * 4 + 2]);
            wp[2] = *reinterpret_cast<const unsigned long long*>(&Ws[b][kk][64 + tcol * 4]);
            wp[3] = *reinterpret_cast<const unsigned long long*>(&Ws[b][kk][64 + tcol * 4 + 2]);
            float a[8] = {a0.x, a0.y, a0.z, a0.w, a1.x, a1.y, a1.z, a1.w};
#pragma unroll
            for (int i = 0; i < 8; i++) {
                unsigned long long ap;
                asm("mov.b64 %0, {%1, %1};" : "=l"(ap) : "f"(a[i]));
#pragma unroll
                for (int j2 = 0; j2 < 4; j2++)
                    asm("fma.rn.f32x2 %0, %1, %2, %0;"
                        : "+l"(accp[i][j2]) : "l"(ap), "l"(wp[j2]));
            }
        }
        // no second barrier: next store targets the other buffer, and passing
        // the NEXT chunk's barrier guarantees this chunk's readers finished.
    }

    float acc[8][8];
#pragma unroll
    for (int i = 0; i < 8; i++)
#pragma unroll
        for (int j2 = 0; j2 < 4; j2++)
            asm("mov.b64 {%0, %1}, %2;"
                : "=f"(acc[i][2 * j2]), "=f"(acc[i][2 * j2 + 1]) : "l"(accp[i][j2]));

    int cidx[8], ridx[8];
#pragma unroll
    for (int j = 0; j < 8; j++)
        cidx[j] = (j < 4) ? (tcol * 4 + j) : (64 + tcol * 4 + (j - 4));
#pragma unroll
    for (int i = 0; i < 8; i++)
        ridx[i] = (i < 4) ? (trow * 4 + i) : (64 + trow * 4 + (i - 4));

    float b[8];
#pragma unroll
    for (int j = 0; j < 8; j++)
        b[j] = bias1[cidx[j]] + (bias2 ? bias2[cidx[j]] : 0.f);

    if (MODE == 0) {
#pragma unroll
        for (int i = 0; i < 8; i++) {
            int grow = row0 + ridx[i];
            if (grow < n_rows) {
#pragma unroll
                for (int j = 0; j < 8; j++)
                    out[(size_t)grow * D + cidx[j]] = fmaxf(acc[i][j] + b[j], 0.f);
            }
        }
    } else {
        float wh[8];
#pragma unroll
        for (int j = 0; j < 8; j++) wh[j] = whead[cidx[j]];
        __syncthreads();
        if (t < 128) red[t] = 0.f;
        __syncthreads();
#pragma unroll
        for (int i = 0; i < 8; i++) {
            float partial = 0.f;
#pragma unroll
            for (int j = 0; j < 8; j++)
                partial += fmaxf(acc[i][j] + b[j], 0.f) * wh[j];
            atomicAdd(&red[ridx[i]], partial);
        }
        __syncthreads();
        if (t < 128) {
            int grow = row0 + t;
            if (grow < n_rows) out[grow] = red[t] + bhead[0];
        }
    }
}

// ---------------------------------------------------------------------------
// Launch: R7's proven 3-branch fork (2 extra streams + 3 events).
// ---------------------------------------------------------------------------
extern "C" void kernel_launch(void* const* d_in, const int* in_sizes, int n_in,
                              void* d_out, int out_size)
{
    const float* x_pfas = (const float*)d_in[0];
    const float* x_gw   = (const float*)d_in[1];
    const float* x_sw   = (const float*)d_in[2];
    const int* ei_pg_src = (const int*)d_in[3];
    const int* ei_pg_dst = (const int*)d_in[4];
    const int* ei_gp_src = (const int*)d_in[5];
    const int* ei_gp_dst = (const int*)d_in[6];
    const int* ei_ps_src = (const int*)d_in[7];
    const int* ei_ps_dst = (const int*)d_in[8];
    const int* ei_sp_src = (const int*)d_in[9];
    const int* ei_sp_dst = (const int*)d_in[10];
    const float* Wl_pg = (const float*)d_in[11];
    const float* bl_pg = (const float*)d_in[12];
    const float* Wr_pg = (const float*)d_in[13];
    const float* Wl_gp = (const float*)d_in[14];
    const float* bl_gp = (const float*)d_in[15];
    const float* Wr_gp = (const float*)d_in[16];
    const float* Wl_ps = (const float*)d_in[17];
    const float* bl_ps = (const float*)d_in[18];
    const float* Wr_ps = (const float*)d_in[19];
    const float* Wl_sp = (const float*)d_in[20];
    const float* bl_sp = (const float*)d_in[21];
    const float* Wr_sp = (const float*)d_in[22];
    const float* W_gw  = (const float*)d_in[23];
    const float* b_gw  = (const float*)d_in[24];
    const float* W_sw  = (const float*)d_in[25];
    const float* b_sw  = (const float*)d_in[26];

    const int E_PG = in_sizes[3];
    const int E_GP = in_sizes[5];
    const int E_PS = in_sizes[7];
    const int E_SP = in_sizes[9];

    float* out = (float*)d_out;
    float* out_hpf = out;                       // [20000, 128]
    float* out_gw  = out + (size_t)NPF * D;     // [100000]
    float* out_sw  = out_gw + NGW;              // [30000]

    static float *mean_gw = nullptr, *mean_sw = nullptr, *mean_gp = nullptr, *mean_sp = nullptr;
    static float *wr_comb = nullptr;
    static int *cnt = nullptr, *rowptr = nullptr, *cursor = nullptr, *perm = nullptr, *partials = nullptr;
    static cudaStream_t s1 = nullptr, s2 = nullptr;
    static cudaEvent_t evRoot = nullptr, ev1 = nullptr, ev2 = nullptr;
    if (!mean_gw) {
        cudaGetSymbolAddress((void**)&mean_gw, g_mean_gw);
        cudaGetSymbolAddress((void**)&mean_sw, g_mean_sw);
        cudaGetSymbolAddress((void**)&mean_gp, g_mean_gp);
        cudaGetSymbolAddress((void**)&mean_sp, g_mean_sp);
        cudaGetSymbolAddress((void**)&wr_comb, g_wr_comb);
        cudaGetSymbolAddress((void**)&cnt, g_cnt);
        cudaGetSymbolAddress((void**)&rowptr, g_rowptr);
        cudaGetSymbolAddress((void**)&cursor, g_cursor);
        cudaGetSymbolAddress((void**)&perm, g_perm);
        cudaGetSymbolAddress((void**)&partials, g_partials);
        cudaStreamCreateWithFlags(&s1, cudaStreamNonBlocking);
        cudaStreamCreateWithFlags(&s2, cudaStreamNonBlocking);
        cudaEventCreateWithFlags(&evRoot, cudaEventDisableTiming);
        cudaEventCreateWithFlags(&ev1, cudaEventDisableTiming);
        cudaEventCreateWithFlags(&ev2, cudaEventDisableTiming);
    }

    const int off_pg = 0;
    const int off_gp = NGW;
    const int off_ps = NGW + NPF;
    const int off_sp = NGW + NPF + NSW;
    const int poff_pg = 0;
    const int poff_gp = E_PG;
    const int poff_ps = E_PG + E_GP;
    const int poff_sp = E_PG + E_GP + E_PS;

    // ---- root: zero all counters on the origin (capture) stream ----
    zero_int_kernel<<<(NTOT / 4 + 255) / 256, 256>>>(cnt, NTOT / 4);
    cudaEventRecord(evRoot, 0);
    cudaStreamWaitEvent(s1, evRoot, 0);
    cudaStreamWaitEvent(s2, evRoot, 0);

    // ================= Branch 1 (stream s1): gw head chain (largest) ========
    {
        hist_kernel<<<(E_PG + 255) / 256, 256, 0, s1>>>(ei_pg_dst, cnt + off_pg, E_PG);
        int nb = (NGW + 1023) / 1024;
        scan_reduce_kernel<<<nb, 256, 0, s1>>>(cnt + off_pg, NGW, partials + 0 * 128);
        scan_partials_kernel<<<1, 128, 0, s1>>>(partials + 0 * 128, nb);
        scan_write_kernel<<<nb, 256, 0, s1>>>(cnt + off_pg, NGW, partials + 0 * 128,
                                              rowptr + off_pg, cursor + off_pg);
        permute_kernel<<<(E_PG + 255) / 256, 256, 0, s1>>>(
            ei_pg_src, ei_pg_dst, cursor + off_pg, perm + poff_pg, E_PG);
        aggregate_kernel<<<(NGW + 7) / 8, 256, 0, s1>>>(
            x_pfas, rowptr + off_pg, perm + poff_pg, mean_gw, NGW, E_PG);
        gemm_fused<2, 1><<<(NGW + 127) / 128, 256, 0, s1>>>(
            mean_gw, x_gw, nullptr,
            Wl_pg, Wr_pg, nullptr,
            bl_pg, nullptr, W_gw, b_gw,
            out_gw, NGW);
    }

    // ================= Branch 2 (stream s2): sw head chain ==================
    {
        hist_kernel<<<(E_PS + 255) / 256, 256, 0, s2>>>(ei_ps_dst, cnt + off_ps, E_PS);
        int nb = (NSW + 1023) / 1024;
        scan_reduce_kernel<<<nb, 256, 0, s2>>>(cnt + off_ps, NSW, partials + 2 * 128);
        scan_partials_kernel<<<1, 128, 0, s2>>>(partials + 2 * 128, nb);
        scan_write_kernel<<<nb, 256, 0, s2>>>(cnt + off_ps, NSW, partials + 2 * 128,
                                              rowptr + off_ps, cursor + off_ps);
        permute_kernel<<<(E_PS + 255) / 256, 256, 0, s2>>>(
            ei_ps_src, ei_ps_dst, cursor + off_ps, perm + poff_ps, E_PS);
        aggregate_kernel<<<(NSW + 7) / 8, 256, 0, s2>>>(
            x_pfas, rowptr + off_ps, perm + poff_ps, mean_sw, NSW, E_PS);
        gemm_fused<2, 1><<<(NSW + 127) / 128, 256, 0, s2>>>(
            mean_sw, x_sw, nullptr,
            Wl_ps, Wr_ps, nullptr,
            bl_ps, nullptr, W_sw, b_sw,
            out_sw, NSW);
    }

    // ================= Branch 0 (origin stream): pfas chain =================
    {
        addw_kernel<<<(D * D + 255) / 256, 256>>>(Wr_gp, Wr_sp, wr_comb);
        hist_kernel<<<(E_GP + 255) / 256, 256>>>(ei_gp_dst, cnt + off_gp, E_GP);
        hist_kernel<<<(E_SP + 255) / 256, 256>>>(ei_sp_dst, cnt + off_sp, E_SP);
        int nb = (NPF + 1023) / 1024;
        scan_reduce_kernel<<<nb, 256>>>(cnt + off_gp, NPF, partials + 1 * 128);
        scan_partials_kernel<<<1, 128>>>(partials + 1 * 128, nb);
        scan_write_kernel<<<nb, 256>>>(cnt + off_gp, NPF, partials + 1 * 128,
                                       rowptr + off_gp, cursor + off_gp);
        scan_reduce_kernel<<<nb, 256>>>(cnt + off_sp, NPF, partials + 3 * 128);
        scan_partials_kernel<<<1, 128>>>(partials + 3 * 128, nb);
        scan_write_kernel<<<nb, 256>>>(cnt + off_sp, NPF, partials + 3 * 128,
                                       rowptr + off_sp, cursor + off_sp);
        permute_kernel<<<(E_GP + 255) / 256, 256>>>(
            ei_gp_src, ei_gp_dst, cursor + off_gp, perm + poff_gp, E_GP);
        permute_kernel<<<(E_SP + 255) / 256, 256>>>(
            ei_sp_src, ei_sp_dst, cursor + off_sp, perm + poff_sp, E_SP);
        aggregate_kernel<<<(NPF + 7) / 8, 256>>>(
            x_gw, rowptr + off_gp, perm + poff_gp, mean_gp, NPF, E_GP);
        aggregate_kernel<<<(NPF + 7) / 8, 256>>>(
            x_sw, rowptr + off_sp, perm + poff_sp, mean_sp, NPF, E_SP);
        gemm_fused<3, 0><<<(NPF + 127) / 128, 256>>>(
            mean_gp, mean_sp, x_pfas,
            Wl_gp, Wl_sp, wr_comb,
            bl_gp, bl_sp, nullptr, nullptr,
            out_hpf, NPF);
    }

    // ---- join branches back to the origin stream ----
    cudaEventRecord(ev1, s1);
    cudaEventRecord(ev2, s2);
    cudaStreamWaitEvent(0, ev1, 0);
    cudaStreamWaitEvent(0, ev2, 0);

    (void)n_in; (void)out_size;
}